// round 3
// baseline (speedup 1.0000x reference)
#include <cuda_runtime.h>
#include <cstdint>

#define NN 2048
#define TT 16
#define DD 16
#define HH 64
#define NP (NN*NN)          // 4194304 pairs
#define NBATCH (NP/32)      // 131072 batches of 32 pairs (8KB each)

// ---------------- device scratch (static, no allocation) ----------------
__device__ __align__(16) float g_E0[NP];          // 16 MB: exp(leaky(rel.w1+b1)+mask)
__device__ __align__(16) float g_emb[NN*HH];      // LSTM last hidden
__device__ __align__(16) float g_era[NN];         // exp(leaky(emb.w2+b2)+leaky(emb.w3+b3))
__device__ __align__(16) float g_zpart[16*NN];    // column-sum partials (16 row-chunks)
__device__ __align__(16) float g_part[8*NN*HH];   // 4 MB partial outputs (8 j-chunks)

__device__ __forceinline__ float sigm(float v) {
    v = fminf(fmaxf(v, -30.f), 30.f);
    return __fdividef(1.f, 1.f + __expf(-v));
}
__device__ __forceinline__ float tanhx(float v) {
    v = fminf(fmaxf(v, -30.f), 30.f);
    float e = __expf(-2.f * v);
    return __fdividef(1.f - e, 1.f + e);
}
__device__ __forceinline__ float leaky(float v) { return fmaxf(0.2f * v, v); }

// ---------------- K1: fused LSTM (warps 0-7 of blocks 0-127) + relation ------
#define K1_BLOCKS 148
#define LSTM_BLOCKS 128
#define K1_THREADS 640
#define NRELW (LSTM_BLOCKS*12 + (K1_BLOCKS-LSTM_BLOCKS)*20)   // 1936 rel warps

// smem float offsets
#define SM_WHH 0          // 64*64*4 floats (layout [(k*64+j)*4 + gate])
#define SM_WIH 16384      // 16*64*4
#define SM_X   20480      // 16 rows * 256
#define SM_H   24576      // 2 * 16 * 64   -> LSTM region ends at 26624
#define SM_LSTM_END 26624
#define SLOT_F 2176       // 32 pairs * 17 float4 * 4 floats
#define SM_W1S 52736      // 26624 + 12*2176 ; w1 (64) + b1 (1) + pad
#define SM_TOT 52808      // floats -> 211232 bytes

__global__ __launch_bounds__(K1_THREADS, 1)
void k1_lstm_rel(const float* __restrict__ x, const float* __restrict__ rel,
                 const float* __restrict__ mask,
                 const float* __restrict__ Wih, const float* __restrict__ Whh,
                 const float* __restrict__ bih, const float* __restrict__ bhh,
                 const float* __restrict__ w1, const float* __restrict__ b1p)
{
    extern __shared__ float sm[];
    const int tid = threadIdx.x;
    const int w = tid >> 5;
    const int bx = blockIdx.x;
    const bool lstmB = (bx < LSTM_BLOCKS);

    if (lstmB && w < 8) {
        // ---------------- LSTM role: 256 threads, 16 rows ----------------
        const int j  = tid & 63;
        const int rg = tid >> 6;
        const int r0 = rg * 4;
        const int row0 = bx * 16;

        float* Whh_P = sm + SM_WHH;
        float* Wih_P = sm + SM_WIH;
        float* x_s   = sm + SM_X;
        float* h_s   = sm + SM_H;

        for (int idx = tid; idx < 16384; idx += 256) {
            int gr = idx >> 6, k = idx & 63;
            int gate = gr >> 6, jj = gr & 63;
            Whh_P[((k << 6) + jj) * 4 + gate] = Whh[idx];
        }
        for (int idx = tid; idx < 4096; idx += 256) {
            int gr = idx >> 4, d = idx & 15;
            int gate = gr >> 6, jj = gr & 63;
            Wih_P[((d << 6) + jj) * 4 + gate] = Wih[idx];
        }
        for (int idx = tid; idx < 16 * TT * DD; idx += 256)
            x_s[idx] = x[(size_t)row0 * TT * DD + idx];
        for (int idx = tid; idx < 2048; idx += 256) h_s[idx] = 0.f;

        float bias_i = bih[j]       + bhh[j];
        float bias_f = bih[64 + j]  + bhh[64 + j];
        float bias_g = bih[128 + j] + bhh[128 + j];
        float bias_o = bih[192 + j] + bhh[192 + j];

        float c[4] = {0.f, 0.f, 0.f, 0.f};
        asm volatile("bar.sync 1, 256;" ::: "memory");

        int buf = 0;
        for (int t = 0; t < TT; t++) {
            float4 a[4];
            #pragma unroll
            for (int q = 0; q < 4; q++) {
                a[q].x = bias_i; a[q].y = bias_f; a[q].z = bias_g; a[q].w = bias_o;
            }
            const float* xb = x_s + t * DD;
            #pragma unroll
            for (int d = 0; d < DD; d++) {
                float4 wi = *(const float4*)(Wih_P + (((d << 6) + j) << 2));
                #pragma unroll
                for (int q = 0; q < 4; q++) {
                    float xv = xb[(r0 + q) * 256 + d];
                    a[q].x = fmaf(wi.x, xv, a[q].x);
                    a[q].y = fmaf(wi.y, xv, a[q].y);
                    a[q].z = fmaf(wi.z, xv, a[q].z);
                    a[q].w = fmaf(wi.w, xv, a[q].w);
                }
            }
            const float* hb = h_s + buf * 1024;
            #pragma unroll 8
            for (int k = 0; k < HH; k++) {
                float4 wh = *(const float4*)(Whh_P + (((k << 6) + j) << 2));
                #pragma unroll
                for (int q = 0; q < 4; q++) {
                    float hv = hb[(r0 + q) * 64 + k];
                    a[q].x = fmaf(wh.x, hv, a[q].x);
                    a[q].y = fmaf(wh.y, hv, a[q].y);
                    a[q].z = fmaf(wh.z, hv, a[q].z);
                    a[q].w = fmaf(wh.w, hv, a[q].w);
                }
            }
            float* hn = h_s + (buf ^ 1) * 1024;
            #pragma unroll
            for (int q = 0; q < 4; q++) {
                float ig = sigm(a[q].x);
                float fg = sigm(a[q].y);
                float gg = tanhx(a[q].z);
                float og = sigm(a[q].w);
                c[q] = fmaf(fg, c[q], ig * gg);
                float hv = og * tanhx(c[q]);
                hn[(r0 + q) * 64 + j] = hv;
                if (t == TT - 1) g_emb[(size_t)(row0 + r0 + q) * 64 + j] = hv;
            }
            asm volatile("bar.sync 1, 256;" ::: "memory");
            buf ^= 1;
        }
    } else {
        // ---------------- relation role: smem transpose, no shuffles ----------
        const int lane = tid & 31;
        const int relw_local = lstmB ? (w - 8) : w;
        const int rw = lstmB ? (bx * 12 + (w - 8))
                             : (LSTM_BLOCKS * 12 + (bx - LSTM_BLOCKS) * 20 + w);
        float4* slot4 = (float4*)(sm + (lstmB ? SM_LSTM_END : 0) + relw_local * SLOT_F);
        const int relcnt = lstmB ? 384 : 640;

        // loader warp fills w1s + b1
        if ((lstmB && w == 8) || (!lstmB && w == 0)) {
            sm[SM_W1S + lane]      = w1[lane];
            sm[SM_W1S + 32 + lane] = w1[32 + lane];
            if (lane == 0) sm[SM_W1S + 64] = __ldg(b1p);
        }
        asm volatile("bar.sync 2, %0;" :: "r"(relcnt) : "memory");

        const float4* w1s4 = (const float4*)(sm + SM_W1S);
        const float b1v = sm[SM_W1S + 64];
        const float4* rel4 = (const float4*)rel;
        const int ph = lane >> 4;          // which pair parity this lane's chunks go to
        const int s  = lane & 15;          // chunk index within pair
        const int me = lane * 17;          // this thread's pair row (float4 units)

        for (int b = rw; b < NBATCH; b += NRELW) {
            const int p = b * 32 + lane;           // this thread's output pair
            float mk = __ldcs(mask + p);           // prefetch mask early

            float4 t[16];
            const float4* src = rel4 + (size_t)b * 512 + lane;
            #pragma unroll
            for (int i = 0; i < 16; i++) t[i] = __ldcs(src + i * 32);
            #pragma unroll
            for (int i = 0; i < 16; i++) slot4[(2 * i + ph) * 17 + s] = t[i];
            __syncwarp();

            float4 a4 = make_float4(0.f, 0.f, 0.f, 0.f);
            #pragma unroll
            for (int k = 0; k < 16; k++) {
                float4 v  = slot4[me + k];
                float4 wv = w1s4[k];
                a4.x = fmaf(v.x, wv.x, a4.x);
                a4.y = fmaf(v.y, wv.y, a4.y);
                a4.z = fmaf(v.z, wv.z, a4.z);
                a4.w = fmaf(v.w, wv.w, a4.w);
            }
            __syncwarp();
            float acc = (a4.x + a4.y) + (a4.z + a4.w);
            g_E0[p] = __expf(leaky(acc + b1v) + mk);
        }
    }
}

// ---------------- K2b: fused era + column-sum partials -----------------------
// grid (NN/256=8, 16): bx = j-block of 256, by = row chunk of 128
__global__ __launch_bounds__(256) void k2b_colsum(
    const float* __restrict__ w2, const float* __restrict__ b2,
    const float* __restrict__ w3, const float* __restrict__ b3)
{
    __shared__ float w2s[64], w3s[64], era_s[128];
    int tid = threadIdx.x;
    if (tid < 64) { w2s[tid] = w2[tid]; w3s[tid] = w3[tid]; }
    __syncthreads();
    int i0 = blockIdx.y * 128;
    if (tid < 128) {
        const float4* e4 = (const float4*)(g_emb + (size_t)(i0 + tid) * 64);
        float s2 = 0.f, s3 = 0.f;
        #pragma unroll
        for (int k = 0; k < 16; k++) {
            float4 e = e4[k];
            float4 a = ((const float4*)w2s)[k];
            float4 b = ((const float4*)w3s)[k];
            s2 += e.x*a.x + e.y*a.y + e.z*a.z + e.w*a.w;
            s3 += e.x*b.x + e.y*b.y + e.z*b.z + e.w*b.w;
        }
        s2 += __ldg(b2); s3 += __ldg(b3);
        float era = __expf(leaky(s2) + leaky(s3));
        era_s[tid] = era;
        if (blockIdx.x == 0) g_era[i0 + tid] = era;
    }
    __syncthreads();
    int j = blockIdx.x * 256 + tid;
    float acc = 0.f;
    #pragma unroll 8
    for (int r = 0; r < 128; r++)
        acc = fmaf(era_s[r], g_E0[(size_t)(i0 + r) * NN + j], acc);
    g_zpart[blockIdx.y * NN + j] = acc;
}

// ---------------- K4: part[jb][i][:] = era_i * sum_j E0[i,j]*iZ_j*emb[j,:] ---
// grid (16, 8), 128 threads; dynamic smem: embz[256*64] + iZ[256]
__global__ __launch_bounds__(128) void k4_prop()
{
    extern __shared__ float dsm[];
    float* embz = dsm;            // 16384 floats
    float* iZ_s = dsm + 16384;    // 256 floats
    int tid = threadIdx.x;
    int i  = blockIdx.x * 128 + tid;
    int j0 = blockIdx.y * 256;

    // iZ for 256 columns
    #pragma unroll
    for (int u = 0; u < 2; u++) {
        int j = tid + u * 128;
        float s = 0.f;
        #pragma unroll
        for (int c = 0; c < 16; c++) s += g_zpart[c * NN + j0 + j];
        iZ_s[j] = __fdividef(1.f, s);
    }
    __syncthreads();
    // embz = emb * iZ (float4 granularity)
    const float4* embg = (const float4*)(g_emb + (size_t)j0 * 64);
    float4* embz4 = (float4*)embz;
    for (int idx = tid; idx < 256 * 16; idx += 128) {
        int j = idx >> 4;
        float4 e = embg[idx];
        float z = iZ_s[j];
        e.x *= z; e.y *= z; e.z *= z; e.w *= z;
        embz4[idx] = e;
    }
    float eri = __ldg(g_era + i);
    __syncthreads();

    // shared-address base for asm LDS
    unsigned int ez_addr;
    asm("{ .reg .u64 t; cvta.to.shared.u64 t, %1; cvt.u32.u64 %0, t; }"
        : "=r"(ez_addr) : "l"(embz));

    unsigned long long acc[32];
    #pragma unroll
    for (int k = 0; k < 32; k++) acc[k] = 0ull;

    const float4* e0 = (const float4*)(g_E0 + (size_t)i * NN + j0);
    for (int jj = 0; jj < 256; jj += 4) {
        float4 ev = __ldg(e0 + (jj >> 2));
        float evv[4] = {ev.x, ev.y, ev.z, ev.w};
        #pragma unroll
        for (int u = 0; u < 4; u++) {
            unsigned long long p2;
            asm("mov.b64 %0, {%1, %1};" : "=l"(p2) : "f"(evv[u]));
            unsigned int base = ez_addr + (jj + u) * 256;   // 64 floats per j
            #pragma unroll
            for (int q = 0; q < 16; q++) {
                unsigned long long z0, z1;
                asm("ld.shared.v2.b64 {%0, %1}, [%2];"
                    : "=l"(z0), "=l"(z1) : "r"(base + q * 16));
                asm("fma.rn.f32x2 %0, %1, %2, %0;" : "+l"(acc[2*q])   : "l"(p2), "l"(z0));
                asm("fma.rn.f32x2 %0, %1, %2, %0;" : "+l"(acc[2*q+1]) : "l"(p2), "l"(z1));
            }
        }
    }
    float* dst = g_part + ((size_t)blockIdx.y * NN + i) * HH;
    #pragma unroll
    for (int k = 0; k < 32; k++) {
        float lo, hi;
        asm("mov.b64 {%0, %1}, %2;" : "=f"(lo), "=f"(hi) : "l"(acc[k]));
        dst[2*k]   = lo * eri;
        dst[2*k+1] = hi * eri;
    }
}

// ---------------- K5: reduce partials + final prediction ---------------------
__global__ void k5_final(const float* __restrict__ w4, const float* __restrict__ b4,
                         float* __restrict__ out)
{
    __shared__ float w4_s[128];
    int tid = threadIdx.x;
    if (tid < 128) w4_s[tid] = w4[tid];
    __syncthreads();
    int i = blockIdx.x * 256 + tid;
    float pred = __ldg(b4);
    const float4* e4 = (const float4*)(g_emb + (size_t)i * 64);
    #pragma unroll
    for (int k = 0; k < 16; k++) {
        float4 e = e4[k];
        float4 wv = ((const float4*)w4_s)[k];
        pred += e.x*wv.x + e.y*wv.y + e.z*wv.z + e.w*wv.w;
    }
    #pragma unroll
    for (int k = 0; k < 16; k++) {
        float4 o = make_float4(0.f, 0.f, 0.f, 0.f);
        #pragma unroll
        for (int cc = 0; cc < 8; cc++) {
            const float4* p4 = (const float4*)(g_part + ((size_t)cc * NN + i) * HH);
            float4 v = p4[k];
            o.x += v.x; o.y += v.y; o.z += v.z; o.w += v.w;
        }
        float4 wv = ((const float4*)w4_s)[16 + k];
        pred += o.x*wv.x + o.y*wv.y + o.z*wv.z + o.w*wv.w;
    }
    out[i] = leaky(pred);
}

// ---------------- launch ------------------------------------------------------
extern "C" void kernel_launch(void* const* d_in, const int* in_sizes, int n_in,
                              void* d_out, int out_size)
{
    const float* x    = (const float*)d_in[0];
    const float* rel  = (const float*)d_in[1];
    const float* mask = (const float*)d_in[2];
    const float* Wih  = (const float*)d_in[3];
    const float* Whh  = (const float*)d_in[4];
    const float* bih  = (const float*)d_in[5];
    const float* bhh  = (const float*)d_in[6];
    const float* w1   = (const float*)d_in[7];
    const float* b1   = (const float*)d_in[8];
    const float* w2   = (const float*)d_in[9];
    const float* b2   = (const float*)d_in[10];
    const float* w3   = (const float*)d_in[11];
    const float* b3   = (const float*)d_in[12];
    const float* w4   = (const float*)d_in[13];
    const float* b4   = (const float*)d_in[14];

    cudaFuncSetAttribute(k1_lstm_rel, cudaFuncAttributeMaxDynamicSharedMemorySize,
                         SM_TOT * (int)sizeof(float));
    cudaFuncSetAttribute(k4_prop, cudaFuncAttributeMaxDynamicSharedMemorySize,
                         (16384 + 256) * (int)sizeof(float));

    k1_lstm_rel<<<K1_BLOCKS, K1_THREADS, SM_TOT * sizeof(float)>>>(
        x, rel, mask, Wih, Whh, bih, bhh, w1, b1);
    k2b_colsum<<<dim3(NN / 256, 16), 256>>>(w2, b2, w3, b3);
    k4_prop<<<dim3(NN / 128, NN / 256), 128, (16384 + 256) * sizeof(float)>>>();
    k5_final<<<NN / 256, 256>>>(w4, b4, (float*)d_out);
}

// round 4
// speedup vs baseline: 1.2988x; 1.2988x over previous
#include <cuda_runtime.h>
#include <cstdint>

#define NN 2048
#define TT 16
#define DD 16
#define HH 64
#define NP (NN*NN)          // 4194304 pairs
#define NP2 (NP/2)          // 2097152 pair-pairs (512B each)

// ---------------- device scratch (static, no allocation) ----------------
__device__ __align__(16) float g_E0[NP];          // 16 MB: exp(leaky(rel.w1+b1)+mask)
__device__ __align__(16) float g_emb[NN*HH];      // LSTM last hidden
__device__ __align__(16) float g_era[NN];         // exp(leaky(emb.w2+b2)+leaky(emb.w3+b3))
__device__ __align__(16) float g_zpart[16*NN];    // column-sum partials (16 row-chunks)
__device__ __align__(16) float g_pp[16*NN];       // per-j-chunk partial predictions

__device__ __forceinline__ float sigm(float v) {
    v = fminf(fmaxf(v, -30.f), 30.f);
    return __fdividef(1.f, 1.f + __expf(-v));
}
__device__ __forceinline__ float tanhx(float v) {
    v = fminf(fmaxf(v, -30.f), 30.f);
    float e = __expf(-2.f * v);
    return __fdividef(1.f - e, 1.f + e);
}
__device__ __forceinline__ float leaky(float v) { return fmaxf(0.2f * v, v); }

// f32x2 helpers
__device__ __forceinline__ void fma2(unsigned long long& acc,
                                     unsigned long long a, unsigned long long b) {
    asm("fma.rn.f32x2 %0, %1, %2, %0;" : "+l"(acc) : "l"(a), "l"(b));
}
__device__ __forceinline__ unsigned long long pk2(float x, float y) {
    unsigned long long r;
    asm("mov.b64 %0, {%1, %2};" : "=l"(r) : "f"(x), "f"(y));
    return r;
}
__device__ __forceinline__ void upk2(float& x, float& y, unsigned long long v) {
    asm("mov.b64 {%0, %1}, %2;" : "=f"(x), "=f"(y) : "l"(v));
}
__device__ __forceinline__ void lds2x64(unsigned long long& a, unsigned long long& b,
                                        unsigned int addr) {
    asm volatile("ld.shared.v2.b64 {%0, %1}, [%2];" : "=l"(a), "=l"(b) : "r"(addr));
}
__device__ __forceinline__ unsigned int smem_u32(const void* p) {
    unsigned int a;
    asm("{ .reg .u64 t; cvta.to.shared.u64 t, %1; cvt.u32.u64 %0, t; }" : "=r"(a) : "l"(p));
    return a;
}

// ---------------- K1: fused LSTM (warps 0-7 of blocks 0-127) + relation ------
#define K1_BLOCKS 148
#define LSTM_BLOCKS 128
#define K1_THREADS 640
#define NRELW (LSTM_BLOCKS*12 + (K1_BLOCKS-LSTM_BLOCKS)*20)   // 1936 rel warps

// smem float offsets (LSTM blocks only use these)
#define SM_WHH 0          // 64*64*4 floats (layout [(k*64+j)*4 + gate])
#define SM_WIH 16384      // 16*64*4
#define SM_X   20480      // 16 rows * 256
#define SM_H   24576      // 2 * 16 * 64
#define SM_TOT 26624      // floats -> 106496 bytes

// process one batch of 16 pair-pairs (32 pairs = 8KB of rel); no smem
__device__ __forceinline__ void rel_batch(
    const float4* __restrict__ rel4, const float* __restrict__ mask,
    long base, int lane, float4 w1v, float b1v, bool guard)
{
    float myS = 0.f;
    #pragma unroll
    for (int half = 0; half < 2; half++) {
        float4 v[8];
        #pragma unroll
        for (int k = 0; k < 8; k++) {
            long p2 = base + half * 8 + k;
            if (!guard || p2 < NP2) v[k] = __ldcs(rel4 + p2 * 32 + lane);
            else v[k] = make_float4(0.f, 0.f, 0.f, 0.f);
        }
        #pragma unroll
        for (int k = 0; k < 8; k++) {
            float s = v[k].x * w1v.x + v[k].y * w1v.y
                    + v[k].z * w1v.z + v[k].w * w1v.w;
            s += __shfl_xor_sync(0xffffffffu, s, 8, 16);
            s += __shfl_xor_sync(0xffffffffu, s, 4, 16);
            s += __shfl_xor_sync(0xffffffffu, s, 2, 16);
            s += __shfl_xor_sync(0xffffffffu, s, 1, 16);
            float got = __shfl_sync(0xffffffffu, s, (lane & 1) << 4);
            int kk = half * 8 + k;
            if ((lane >> 1) == kk) myS = got;
        }
    }
    long p = 2 * base + lane;
    if (!guard || p < NP) {
        float mk = __ldcs(mask + p);
        g_E0[p] = __expf(leaky(myS + b1v) + mk);
    }
}

__global__ __launch_bounds__(K1_THREADS, 1)
void k1_lstm_rel(const float* __restrict__ x, const float* __restrict__ rel,
                 const float* __restrict__ mask,
                 const float* __restrict__ Wih, const float* __restrict__ Whh,
                 const float* __restrict__ bih, const float* __restrict__ bhh,
                 const float* __restrict__ w1, const float* __restrict__ b1p)
{
    extern __shared__ float sm[];
    const int tid = threadIdx.x;
    const int w = tid >> 5;
    const int bx = blockIdx.x;
    const bool lstmB = (bx < LSTM_BLOCKS);

    if (lstmB && w < 8) {
        // ---------------- LSTM role: 256 threads, 16 rows, f32x2 gates -------
        const int j  = tid & 63;
        const int rg = tid >> 6;
        const int r0 = rg * 4;
        const int row0 = bx * 16;

        float* Whh_P = sm + SM_WHH;
        float* Wih_P = sm + SM_WIH;
        float* x_s   = sm + SM_X;
        float* h_s   = sm + SM_H;

        for (int idx = tid; idx < 16384; idx += 256) {
            int gr = idx >> 6, k = idx & 63;
            int gate = gr >> 6, jj = gr & 63;
            Whh_P[((k << 6) + jj) * 4 + gate] = Whh[idx];
        }
        for (int idx = tid; idx < 4096; idx += 256) {
            int gr = idx >> 4, d = idx & 15;
            int gate = gr >> 6, jj = gr & 63;
            Wih_P[((d << 6) + jj) * 4 + gate] = Wih[idx];
        }
        for (int idx = tid; idx < 16 * TT * DD; idx += 256)
            x_s[idx] = x[(size_t)row0 * TT * DD + idx];
        for (int idx = tid; idx < 2048; idx += 256) h_s[idx] = 0.f;

        const unsigned long long bIF = pk2(bih[j] + bhh[j], bih[64 + j] + bhh[64 + j]);
        const unsigned long long bGO = pk2(bih[128 + j] + bhh[128 + j], bih[192 + j] + bhh[192 + j]);

        const unsigned int wih_a = smem_u32(Wih_P) + (unsigned)j * 16;
        const unsigned int whh_a = smem_u32(Whh_P) + (unsigned)j * 16;

        float c[4] = {0.f, 0.f, 0.f, 0.f};
        asm volatile("bar.sync 1, 256;" ::: "memory");

        int buf = 0;
        for (int t = 0; t < TT; t++) {
            unsigned long long aIF[4], aGO[4];
            #pragma unroll
            for (int q = 0; q < 4; q++) { aIF[q] = bIF; aGO[q] = bGO; }

            const float* xb = x_s + t * DD;
            #pragma unroll
            for (int d = 0; d < DD; d++) {
                unsigned long long wIF, wGO;
                lds2x64(wIF, wGO, wih_a + (unsigned)d * 1024);
                #pragma unroll
                for (int q = 0; q < 4; q++) {
                    float xv = xb[(r0 + q) * 256 + d];
                    unsigned long long x2 = pk2(xv, xv);
                    fma2(aIF[q], wIF, x2);
                    fma2(aGO[q], wGO, x2);
                }
            }
            const float* hb = h_s + buf * 1024;
            #pragma unroll 8
            for (int k = 0; k < HH; k++) {
                unsigned long long wIF, wGO;
                lds2x64(wIF, wGO, whh_a + (unsigned)k * 1024);
                #pragma unroll
                for (int q = 0; q < 4; q++) {
                    float hv = hb[(r0 + q) * 64 + k];
                    unsigned long long h2 = pk2(hv, hv);
                    fma2(aIF[q], wIF, h2);
                    fma2(aGO[q], wGO, h2);
                }
            }
            float* hn = h_s + (buf ^ 1) * 1024;
            #pragma unroll
            for (int q = 0; q < 4; q++) {
                float ai, af, ag, ao;
                upk2(ai, af, aIF[q]);
                upk2(ag, ao, aGO[q]);
                float ig = sigm(ai);
                float fg = sigm(af);
                float gg = tanhx(ag);
                float og = sigm(ao);
                c[q] = fmaf(fg, c[q], ig * gg);
                float hv = og * tanhx(c[q]);
                hn[(r0 + q) * 64 + j] = hv;
                if (t == TT - 1) g_emb[(size_t)(row0 + r0 + q) * 64 + j] = hv;
            }
            asm volatile("bar.sync 1, 256;" ::: "memory");
            buf ^= 1;
        }
    } else {
        // ---------------- relation role: global-only, shuffle reduce ---------
        const int rw = lstmB ? (bx * 12 + (w - 8))
                             : (LSTM_BLOCKS * 12 + (bx - LSTM_BLOCKS) * 20 + w);
        const int lane = tid & 31;
        const int sub  = lane & 15;
        float4 w1v = *(const float4*)(w1 + sub * 4);
        float b1v = __ldg(b1p);
        const float4* rel4 = (const float4*)rel;

        const long stride = (long)NRELW * 16;
        long base = (long)rw * 16;
        for (; base + 16 <= NP2; base += stride)
            rel_batch(rel4, mask, base, lane, w1v, b1v, false);
        if (base < NP2)
            rel_batch(rel4, mask, base, lane, w1v, b1v, true);
    }
}

// ---------------- K2b: fused era + column-sum partials -----------------------
// grid (NN/256=8, 16): bx = j-block of 256, by = row chunk of 128
__global__ __launch_bounds__(256) void k2b_colsum(
    const float* __restrict__ w2, const float* __restrict__ b2,
    const float* __restrict__ w3, const float* __restrict__ b3)
{
    __shared__ float w2s[64], w3s[64], era_s[128];
    int tid = threadIdx.x;
    if (tid < 64) { w2s[tid] = w2[tid]; w3s[tid] = w3[tid]; }
    __syncthreads();
    int i0 = blockIdx.y * 128;
    if (tid < 128) {
        const float4* e4 = (const float4*)(g_emb + (size_t)(i0 + tid) * 64);
        float s2 = 0.f, s3 = 0.f;
        #pragma unroll
        for (int k = 0; k < 16; k++) {
            float4 e = e4[k];
            float4 a = ((const float4*)w2s)[k];
            float4 b = ((const float4*)w3s)[k];
            s2 += e.x*a.x + e.y*a.y + e.z*a.z + e.w*a.w;
            s3 += e.x*b.x + e.y*b.y + e.z*b.z + e.w*b.w;
        }
        s2 += __ldg(b2); s3 += __ldg(b3);
        float era = __expf(leaky(s2) + leaky(s3));
        era_s[tid] = era;
        if (blockIdx.x == 0) g_era[i0 + tid] = era;
    }
    __syncthreads();
    int j = blockIdx.x * 256 + tid;
    float acc = 0.f;
    #pragma unroll 8
    for (int r = 0; r < 128; r++)
        acc = fmaf(era_s[r], g_E0[(size_t)(i0 + r) * NN + j], acc);
    g_zpart[blockIdx.y * NN + j] = acc;
}

// ---------------- K4: pp[jc][i] = eri * (sum_j E0[i,j]*iZ_j*emb[j,:]) . w4b --
// grid (16, 16), 128 threads: bx = i-tile of 128, by = j-chunk of 128
__global__ __launch_bounds__(128) void k4_prop(const float* __restrict__ w4)
{
    __shared__ float embz[128 * 64];   // emb * iZ for this j-chunk
    __shared__ float iZ_s[128];
    __shared__ float w4b_s[64];
    int tid = threadIdx.x;
    int i  = blockIdx.x * 128 + tid;
    int j0 = blockIdx.y * 128;

    if (tid < 64) w4b_s[tid] = w4[64 + tid];
    // iZ for this chunk's 128 columns
    {
        float s = 0.f;
        #pragma unroll
        for (int c = 0; c < 16; c++) s += g_zpart[c * NN + j0 + tid];
        iZ_s[tid] = __fdividef(1.f, s);
    }
    __syncthreads();
    const float4* embg = (const float4*)(g_emb + (size_t)j0 * 64);
    float4* embz4 = (float4*)embz;
    for (int idx = tid; idx < 128 * 16; idx += 128) {
        int j = idx >> 4;
        float4 e = embg[idx];
        float z = iZ_s[j];
        e.x *= z; e.y *= z; e.z *= z; e.w *= z;
        embz4[idx] = e;
    }
    float eri = __ldg(g_era + i);
    __syncthreads();

    unsigned int ez_addr = smem_u32(embz);

    unsigned long long acc[32];
    #pragma unroll
    for (int k = 0; k < 32; k++) acc[k] = 0ull;

    const float4* e0 = (const float4*)(g_E0 + (size_t)i * NN + j0);
    for (int jj = 0; jj < 128; jj += 4) {
        float4 ev = __ldg(e0 + (jj >> 2));
        float evv[4] = {ev.x, ev.y, ev.z, ev.w};
        #pragma unroll
        for (int u = 0; u < 4; u++) {
            unsigned long long p2 = pk2(evv[u], evv[u]);
            unsigned int base = ez_addr + (jj + u) * 256;   // 64 floats per j
            #pragma unroll
            for (int q = 0; q < 16; q++) {
                unsigned long long z0, z1;
                lds2x64(z0, z1, base + q * 16);
                fma2(acc[2*q],   p2, z0);
                fma2(acc[2*q+1], p2, z1);
            }
        }
    }
    // epilogue: dot 64-vector accumulator with w4b, scale by eri
    float pp = 0.f;
    #pragma unroll
    for (int k = 0; k < 32; k++) {
        float lo, hi;
        upk2(lo, hi, acc[k]);
        pp += lo * w4b_s[2*k] + hi * w4b_s[2*k+1];
    }
    g_pp[(size_t)blockIdx.y * NN + i] = pp * eri;
}

// ---------------- K5: out[i] = leaky(b4 + emb.w4a + sum_c pp[c][i]) ----------
__global__ __launch_bounds__(128) void k5_final(const float* __restrict__ w4,
                                                const float* __restrict__ b4,
                                                float* __restrict__ out)
{
    __shared__ float w4a[64];
    int tid = threadIdx.x;
    if (tid < 64) w4a[tid] = w4[tid];
    __syncthreads();
    int i = blockIdx.x * 128 + tid;
    float pred = __ldg(b4);
    const float4* e4 = (const float4*)(g_emb + (size_t)i * 64);
    #pragma unroll
    for (int k = 0; k < 16; k++) {
        float4 e = e4[k];
        float4 wv = ((const float4*)w4a)[k];
        pred += e.x*wv.x + e.y*wv.y + e.z*wv.z + e.w*wv.w;
    }
    float s = 0.f;
    #pragma unroll
    for (int c = 0; c < 16; c++) s += g_pp[(size_t)c * NN + i];
    out[i] = leaky(pred + s);
}

// ---------------- launch ------------------------------------------------------
extern "C" void kernel_launch(void* const* d_in, const int* in_sizes, int n_in,
                              void* d_out, int out_size)
{
    const float* x    = (const float*)d_in[0];
    const float* rel  = (const float*)d_in[1];
    const float* mask = (const float*)d_in[2];
    const float* Wih  = (const float*)d_in[3];
    const float* Whh  = (const float*)d_in[4];
    const float* bih  = (const float*)d_in[5];
    const float* bhh  = (const float*)d_in[6];
    const float* w1   = (const float*)d_in[7];
    const float* b1   = (const float*)d_in[8];
    const float* w2   = (const float*)d_in[9];
    const float* b2   = (const float*)d_in[10];
    const float* w3   = (const float*)d_in[11];
    const float* b3   = (const float*)d_in[12];
    const float* w4   = (const float*)d_in[13];
    const float* b4   = (const float*)d_in[14];

    cudaFuncSetAttribute(k1_lstm_rel, cudaFuncAttributeMaxDynamicSharedMemorySize,
                         SM_TOT * (int)sizeof(float));

    k1_lstm_rel<<<K1_BLOCKS, K1_THREADS, SM_TOT * sizeof(float)>>>(
        x, rel, mask, Wih, Whh, bih, bhh, w1, b1);
    k2b_colsum<<<dim3(NN / 256, 16), 256>>>(w2, b2, w3, b3);
    k4_prop<<<dim3(NN / 128, NN / 128), 128>>>(w4);
    k5_final<<<NN / 128, 128>>>(w4, b4, (float*)d_out);
}

// round 7
// speedup vs baseline: 1.5201x; 1.1704x over previous
#include <cuda_runtime.h>
#include <cstdint>

#define NN 2048
#define TT 16
#define DD 16
#define HH 64
#define NP (NN*NN)          // 4194304 pairs
#define NP2 (NP/2)          // 2097152 pair-pairs (512B each)

// ---------------- device scratch (static, no allocation) ----------------
__device__ __align__(16) float g_E0[NP];          // 16 MB: exp(leaky(rel.w1+b1)+mask)
__device__ __align__(16) float g_emb[NN*HH];      // LSTM last hidden
__device__ __align__(16) float g_era[NN];         // exp(leaky(emb.w2+b2)+leaky(emb.w3+b3))
__device__ __align__(16) float g_zpart[16*NN];    // column-sum partials (16 row-chunks)
__device__ __align__(16) float g_pp[16*NN];       // per-j-chunk partial predictions

__device__ __forceinline__ float sigm(float v) {
    v = fminf(fmaxf(v, -30.f), 30.f);
    return __fdividef(1.f, 1.f + __expf(-v));
}
__device__ __forceinline__ float tanhx(float v) {
    v = fminf(fmaxf(v, -30.f), 30.f);
    float e = __expf(-2.f * v);
    return __fdividef(1.f - e, 1.f + e);
}
__device__ __forceinline__ float leaky(float v) { return fmaxf(0.2f * v, v); }

// f32x2 helpers
__device__ __forceinline__ void fma2(unsigned long long& acc,
                                     unsigned long long a, unsigned long long b) {
    asm("fma.rn.f32x2 %0, %1, %2, %0;" : "+l"(acc) : "l"(a), "l"(b));
}
__device__ __forceinline__ unsigned long long pk2(float x, float y) {
    unsigned long long r;
    asm("mov.b64 %0, {%1, %2};" : "=l"(r) : "f"(x), "f"(y));
    return r;
}
__device__ __forceinline__ void upk2(float& x, float& y, unsigned long long v) {
    asm("mov.b64 {%0, %1}, %2;" : "=f"(x), "=f"(y) : "l"(v));
}
__device__ __forceinline__ void lds2x64(unsigned long long& a, unsigned long long& b,
                                        unsigned int addr) {
    asm volatile("ld.shared.v2.b64 {%0, %1}, [%2];" : "=l"(a), "=l"(b) : "r"(addr));
}
__device__ __forceinline__ unsigned int smem_u32(const void* p) {
    unsigned int a;
    asm("{ .reg .u64 t; cvta.to.shared.u64 t, %1; cvt.u32.u64 %0, t; }" : "=r"(a) : "l"(p));
    return a;
}

// ---------------- K1: fused LSTM (warps 0-7 of blocks 0-127) + relation ------
#define K1_BLOCKS 148
#define LSTM_BLOCKS 128
#define K1_THREADS 768
#define NRELW (LSTM_BLOCKS*16 + (K1_BLOCKS-LSTM_BLOCKS)*24)   // 2528 rel warps

// smem float offsets (LSTM blocks only use these)
#define SM_WHH 0          // 64*64*4 floats (layout [(k*64+j)*4 + gate])
#define SM_WIH 16384      // 16*64*4
#define SM_X   20480      // 16 rows * 256
#define SM_H   24576      // 2 * 16 * 64
#define SM_TOT 26624      // floats -> 106496 bytes

// process one batch of 16 pair-pairs (32 pairs = 8KB of rel); no smem
// permuted in-line store: lane keeps pair 2*(lane&15) + (lane>>4)
__device__ __forceinline__ void rel_batch(
    const float4* __restrict__ rel4, const float* __restrict__ mask,
    long base, int lane, float4 w1v, float b1v, bool guard)
{
    const int myk = lane & 15;
    long p = 2 * base + 2 * myk + (lane >> 4);
    float mk = 0.f;
    if (!guard || p < NP) mk = __ldcs(mask + p);

    float myS = 0.f;
    #pragma unroll
    for (int half = 0; half < 2; half++) {
        float4 v[8];
        #pragma unroll
        for (int k = 0; k < 8; k++) {
            long p2 = base + half * 8 + k;
            if (!guard || p2 < NP2) v[k] = __ldcs(rel4 + p2 * 32 + lane);
            else v[k] = make_float4(0.f, 0.f, 0.f, 0.f);
        }
        #pragma unroll
        for (int k = 0; k < 8; k++) {
            float s = v[k].x * w1v.x + v[k].y * w1v.y
                    + v[k].z * w1v.z + v[k].w * w1v.w;
            // width-16 XOR butterfly = allreduce within each 16-lane half
            s += __shfl_xor_sync(0xffffffffu, s, 8, 16);
            s += __shfl_xor_sync(0xffffffffu, s, 4, 16);
            s += __shfl_xor_sync(0xffffffffu, s, 2, 16);
            s += __shfl_xor_sync(0xffffffffu, s, 1, 16);
            int kk = half * 8 + k;     // computed pairs 2*kk (h=0) / 2*kk+1 (h=1)
            if (myk == kk) myS = s;    // lane keeps its own pair's sum
        }
    }
    if (!guard || p < NP)
        g_E0[p] = __expf(leaky(myS + b1v) + mk);
}

__global__ __launch_bounds__(K1_THREADS, 1)
void k1_lstm_rel(const float* __restrict__ x, const float* __restrict__ rel,
                 const float* __restrict__ mask,
                 const float* __restrict__ Wih, const float* __restrict__ Whh,
                 const float* __restrict__ bih, const float* __restrict__ bhh,
                 const float* __restrict__ w1, const float* __restrict__ b1p)
{
    extern __shared__ float sm[];
    const int tid = threadIdx.x;
    const int w = tid >> 5;
    const int bx = blockIdx.x;
    const bool lstmB = (bx < LSTM_BLOCKS);

    if (lstmB && w < 8) {
        // ---------------- LSTM role: 256 threads, 16 rows, f32x2 gates -------
        // (R4-proven memory pattern: scalar operand loads, v2.b64 weight loads)
        const int j  = tid & 63;
        const int rg = tid >> 6;
        const int r0 = rg * 4;
        const int row0 = bx * 16;

        float* Whh_P = sm + SM_WHH;
        float* Wih_P = sm + SM_WIH;
        float* x_s   = sm + SM_X;
        float* h_s   = sm + SM_H;

        for (int idx = tid; idx < 16384; idx += 256) {
            int gr = idx >> 6, k = idx & 63;
            int gate = gr >> 6, jj = gr & 63;
            Whh_P[((k << 6) + jj) * 4 + gate] = Whh[idx];
        }
        for (int idx = tid; idx < 4096; idx += 256) {
            int gr = idx >> 4, d = idx & 15;
            int gate = gr >> 6, jj = gr & 63;
            Wih_P[((d << 6) + jj) * 4 + gate] = Wih[idx];
        }
        for (int idx = tid; idx < 16 * TT * DD; idx += 256)
            x_s[idx] = x[(size_t)row0 * TT * DD + idx];
        for (int idx = tid; idx < 2048; idx += 256) h_s[idx] = 0.f;

        const unsigned long long bIF = pk2(bih[j] + bhh[j], bih[64 + j] + bhh[64 + j]);
        const unsigned long long bGO = pk2(bih[128 + j] + bhh[128 + j], bih[192 + j] + bhh[192 + j]);

        const unsigned int wih_a = smem_u32(Wih_P) + (unsigned)j * 16;
        const unsigned int whh_a = smem_u32(Whh_P) + (unsigned)j * 16;

        float c[4] = {0.f, 0.f, 0.f, 0.f};
        asm volatile("bar.sync 1, 256;" ::: "memory");

        int buf = 0;
        for (int t = 0; t < TT; t++) {
            unsigned long long aIF[4], aGO[4];
            #pragma unroll
            for (int q = 0; q < 4; q++) { aIF[q] = bIF; aGO[q] = bGO; }

            const float* xb = x_s + t * DD;
            #pragma unroll
            for (int d = 0; d < DD; d++) {
                unsigned long long wIF, wGO;
                lds2x64(wIF, wGO, wih_a + (unsigned)d * 1024);
                #pragma unroll
                for (int q = 0; q < 4; q++) {
                    float xv = xb[(r0 + q) * 256 + d];
                    unsigned long long x2 = pk2(xv, xv);
                    fma2(aIF[q], wIF, x2);
                    fma2(aGO[q], wGO, x2);
                }
            }
            const float* hb = h_s + buf * 1024;
            #pragma unroll 8
            for (int k = 0; k < HH; k++) {
                unsigned long long wIF, wGO;
                lds2x64(wIF, wGO, whh_a + (unsigned)k * 1024);
                #pragma unroll
                for (int q = 0; q < 4; q++) {
                    float hv = hb[(r0 + q) * 64 + k];
                    unsigned long long h2 = pk2(hv, hv);
                    fma2(aIF[q], wIF, h2);
                    fma2(aGO[q], wGO, h2);
                }
            }
            float* hn = h_s + (buf ^ 1) * 1024;
            #pragma unroll
            for (int q = 0; q < 4; q++) {
                float ai, af, ag, ao;
                upk2(ai, af, aIF[q]);
                upk2(ag, ao, aGO[q]);
                float ig = sigm(ai);
                float fg = sigm(af);
                float gg = tanhx(ag);
                float og = sigm(ao);
                c[q] = fmaf(fg, c[q], ig * gg);
                float hv = og * tanhx(c[q]);
                hn[(r0 + q) * 64 + j] = hv;
                if (t == TT - 1) g_emb[(size_t)(row0 + r0 + q) * 64 + j] = hv;
            }
            asm volatile("bar.sync 1, 256;" ::: "memory");
            buf ^= 1;
        }
    } else {
        // ---------------- relation role: global-only, shuffle reduce ---------
        const int rw = lstmB ? (bx * 16 + (w - 8))
                             : (LSTM_BLOCKS * 16 + (bx - LSTM_BLOCKS) * 24 + w);
        const int lane = tid & 31;
        const int sub  = lane & 15;
        float4 w1v = *(const float4*)(w1 + sub * 4);
        float b1v = __ldg(b1p);
        const float4* rel4 = (const float4*)rel;

        const long stride = (long)NRELW * 16;
        long base = (long)rw * 16;
        for (; base + 16 <= NP2; base += stride)
            rel_batch(rel4, mask, base, lane, w1v, b1v, false);
        if (base < NP2)
            rel_batch(rel4, mask, base, lane, w1v, b1v, true);
    }
}

// ---------------- K2b: fused era + column-sum partials (R4-proven) -----------
// grid (NN/256=8, 16): bx = j-block of 256, by = row chunk of 128
__global__ __launch_bounds__(256) void k2b_colsum(
    const float* __restrict__ w2, const float* __restrict__ b2,
    const float* __restrict__ w3, const float* __restrict__ b3)
{
    __shared__ float w2s[64], w3s[64], era_s[128];
    int tid = threadIdx.x;
    if (tid < 64) { w2s[tid] = w2[tid]; w3s[tid] = w3[tid]; }
    __syncthreads();
    int i0 = blockIdx.y * 128;
    if (tid < 128) {
        const float4* e4 = (const float4*)(g_emb + (size_t)(i0 + tid) * 64);
        float s2 = 0.f, s3 = 0.f;
        #pragma unroll
        for (int k = 0; k < 16; k++) {
            float4 e = e4[k];
            float4 a = ((const float4*)w2s)[k];
            float4 b = ((const float4*)w3s)[k];
            s2 += e.x*a.x + e.y*a.y + e.z*a.z + e.w*a.w;
            s3 += e.x*b.x + e.y*b.y + e.z*b.z + e.w*b.w;
        }
        s2 += __ldg(b2); s3 += __ldg(b3);
        float era = __expf(leaky(s2) + leaky(s3));
        era_s[tid] = era;
        if (blockIdx.x == 0) g_era[i0 + tid] = era;
    }
    __syncthreads();
    int j = blockIdx.x * 256 + tid;
    float acc = 0.f;
    #pragma unroll 8
    for (int r = 0; r < 128; r++)
        acc = fmaf(era_s[r], g_E0[(size_t)(i0 + r) * NN + j], acc);
    g_zpart[blockIdx.y * NN + j] = acc;
}

// ---------------- K4: pp[jc][i] = eri * (sum_j E0[i,j]*iZ_j*emb[j,:]) . w4b --
// grid (16, 16), 128 threads: bx = i-tile of 128, by = j-chunk of 128 (R4-proven)
__global__ __launch_bounds__(128) void k4_prop(const float* __restrict__ w4)
{
    __shared__ float embz[128 * 64];   // emb * iZ for this j-chunk
    __shared__ float iZ_s[128];
    __shared__ float w4b_s[64];
    int tid = threadIdx.x;
    int i  = blockIdx.x * 128 + tid;
    int j0 = blockIdx.y * 128;

    if (tid < 64) w4b_s[tid] = w4[64 + tid];
    // iZ for this chunk's 128 columns
    {
        float s = 0.f;
        #pragma unroll
        for (int c = 0; c < 16; c++) s += g_zpart[c * NN + j0 + tid];
        iZ_s[tid] = __fdividef(1.f, s);
    }
    __syncthreads();
    const float4* embg = (const float4*)(g_emb + (size_t)j0 * 64);
    float4* embz4 = (float4*)embz;
    for (int idx = tid; idx < 128 * 16; idx += 128) {
        int j = idx >> 4;
        float4 e = embg[idx];
        float z = iZ_s[j];
        e.x *= z; e.y *= z; e.z *= z; e.w *= z;
        embz4[idx] = e;
    }
    float eri = __ldg(g_era + i);
    __syncthreads();

    unsigned int ez_addr = smem_u32(embz);

    unsigned long long acc[32];
    #pragma unroll
    for (int k = 0; k < 32; k++) acc[k] = 0ull;

    const float4* e0 = (const float4*)(g_E0 + (size_t)i * NN + j0);
    for (int jj = 0; jj < 128; jj += 4) {
        float4 ev = __ldg(e0 + (jj >> 2));
        float evv[4] = {ev.x, ev.y, ev.z, ev.w};
        #pragma unroll
        for (int u = 0; u < 4; u++) {
            unsigned long long p2 = pk2(evv[u], evv[u]);
            unsigned int base = ez_addr + (jj + u) * 256;   // 64 floats per j
            #pragma unroll
            for (int q = 0; q < 16; q++) {
                unsigned long long z0, z1;
                lds2x64(z0, z1, base + q * 16);
                fma2(acc[2*q],   p2, z0);
                fma2(acc[2*q+1], p2, z1);
            }
        }
    }
    // epilogue: dot 64-vector accumulator with w4b, scale by eri
    float pp = 0.f;
    #pragma unroll
    for (int k = 0; k < 32; k++) {
        float lo, hi;
        upk2(lo, hi, acc[k]);
        pp += lo * w4b_s[2*k] + hi * w4b_s[2*k+1];
    }
    g_pp[(size_t)blockIdx.y * NN + i] = pp * eri;
}

// ---------------- K5: out[i] = leaky(b4 + emb.w4a + sum_c pp[c][i]) ----------
__global__ __launch_bounds__(128) void k5_final(const float* __restrict__ w4,
                                                const float* __restrict__ b4,
                                                float* __restrict__ out)
{
    __shared__ float w4a[64];
    int tid = threadIdx.x;
    if (tid < 64) w4a[tid] = w4[tid];
    __syncthreads();
    int i = blockIdx.x * 128 + tid;
    float pred = __ldg(b4);
    const float4* e4 = (const float4*)(g_emb + (size_t)i * 64);
    #pragma unroll
    for (int k = 0; k < 16; k++) {
        float4 e = e4[k];
        float4 wv = ((const float4*)w4a)[k];
        pred += e.x*wv.x + e.y*wv.y + e.z*wv.z + e.w*wv.w;
    }
    float s = 0.f;
    #pragma unroll
    for (int c = 0; c < 16; c++) s += g_pp[(size_t)c * NN + i];
    out[i] = leaky(pred + s);
}

// ---------------- launch ------------------------------------------------------
extern "C" void kernel_launch(void* const* d_in, const int* in_sizes, int n_in,
                              void* d_out, int out_size)
{
    const float* x    = (const float*)d_in[0];
    const float* rel  = (const float*)d_in[1];
    const float* mask = (const float*)d_in[2];
    const float* Wih  = (const float*)d_in[3];
    const float* Whh  = (const float*)d_in[4];
    const float* bih  = (const float*)d_in[5];
    const float* bhh  = (const float*)d_in[6];
    const float* w1   = (const float*)d_in[7];
    const float* b1   = (const float*)d_in[8];
    const float* w2   = (const float*)d_in[9];
    const float* b2   = (const float*)d_in[10];
    const float* w3   = (const float*)d_in[11];
    const float* b3   = (const float*)d_in[12];
    const float* w4   = (const float*)d_in[13];
    const float* b4   = (const float*)d_in[14];

    cudaFuncSetAttribute(k1_lstm_rel, cudaFuncAttributeMaxDynamicSharedMemorySize,
                         SM_TOT * (int)sizeof(float));

    k1_lstm_rel<<<K1_BLOCKS, K1_THREADS, SM_TOT * sizeof(float)>>>(
        x, rel, mask, Wih, Whh, bih, bhh, w1, b1);
    k2b_colsum<<<dim3(NN / 256, 16), 256>>>(w2, b2, w3, b3);
    k4_prop<<<dim3(NN / 128, NN / 128), 128>>>(w4);
    k5_final<<<NN / 128, 128>>>(w4, b4, (float*)d_out);
}

// round 9
// speedup vs baseline: 1.7449x; 1.1479x over previous
#include <cuda_runtime.h>
#include <cstdint>

#define NN 2048
#define TT 16
#define DD 16
#define HH 64
#define NP (NN*NN)          // 4194304 pairs
#define NP2 (NP/2)          // 2097152 pair-pairs (512B each)

// ---------------- device scratch (static, no allocation) ----------------
__device__ __align__(16) float g_E0[NP];          // 16 MB: exp(leaky(rel.w1+b1)+mask)
__device__ __align__(16) float g_emb[NN*HH];      // LSTM last hidden
__device__ __align__(16) float g_era[NN];         // exp(leaky(emb.w2+b2)+leaky(emb.w3+b3))
__device__ __align__(16) float g_zpart[16*NN];    // column-sum partials (16 row-chunks)
__device__ __align__(16) float g_q[NN];           // iZ_j * (emb[j].w4b)
__device__ __align__(16) float g_base[NN];        // b4 + emb[j].w4a

__device__ __forceinline__ float sigm(float v) {
    v = fminf(fmaxf(v, -30.f), 30.f);
    return __fdividef(1.f, 1.f + __expf(-v));
}
__device__ __forceinline__ float tanhx(float v) {
    v = fminf(fmaxf(v, -30.f), 30.f);
    float e = __expf(-2.f * v);
    return __fdividef(1.f - e, 1.f + e);
}
__device__ __forceinline__ float leaky(float v) { return fmaxf(0.2f * v, v); }

// f32x2 helpers
__device__ __forceinline__ void fma2(unsigned long long& acc,
                                     unsigned long long a, unsigned long long b) {
    asm("fma.rn.f32x2 %0, %1, %2, %0;" : "+l"(acc) : "l"(a), "l"(b));
}
__device__ __forceinline__ unsigned long long pk2(float x, float y) {
    unsigned long long r;
    asm("mov.b64 %0, {%1, %2};" : "=l"(r) : "f"(x), "f"(y));
    return r;
}
__device__ __forceinline__ void upk2(float& x, float& y, unsigned long long v) {
    asm("mov.b64 {%0, %1}, %2;" : "=f"(x), "=f"(y) : "l"(v));
}
__device__ __forceinline__ void lds2x64(unsigned long long& a, unsigned long long& b,
                                        unsigned int addr) {
    asm volatile("ld.shared.v2.b64 {%0, %1}, [%2];" : "=l"(a), "=l"(b) : "r"(addr));
}
__device__ __forceinline__ unsigned int smem_u32(const void* p) {
    unsigned int a;
    asm("{ .reg .u64 t; cvta.to.shared.u64 t, %1; cvt.u32.u64 %0, t; }" : "=r"(a) : "l"(p));
    return a;
}

// ---------------- K1: fused LSTM (warps 0-7 of blocks 0-127) + relation ------
#define K1_BLOCKS 148
#define LSTM_BLOCKS 128
#define K1_THREADS 768
#define NRELW (LSTM_BLOCKS*16 + (K1_BLOCKS-LSTM_BLOCKS)*24)   // 2528 rel warps

// smem float offsets (LSTM blocks only use these)
#define SM_WHH 0          // 64*64*4 floats (layout [(k*64+j)*4 + gate])
#define SM_WIH 16384      // 16*64*4
#define SM_X   20480      // 16 rows * 256
#define SM_H   24576      // 2 * 16 * 64
#define SM_TOT 26624      // floats -> 106496 bytes

// process one batch of 16 pair-pairs (32 pairs = 8KB of rel); no smem
// all 16 LDG.128 issued before compute (MLP=16); lane keeps pair 2*(lane&15)+(lane>>4)
__device__ __forceinline__ void rel_batch(
    const float4* __restrict__ rel4, const float* __restrict__ mask,
    long base, int lane, float4 w1v, float b1v, bool guard)
{
    const int myk = lane & 15;
    long p = 2 * base + 2 * myk + (lane >> 4);
    float mk = 0.f;
    if (!guard || p < NP) mk = __ldcs(mask + p);

    float4 v[16];
    const float4* src = rel4 + base * 32 + lane;
    #pragma unroll
    for (int k = 0; k < 16; k++) {
        if (!guard || base + k < NP2) v[k] = __ldcs(src + k * 32);
        else v[k] = make_float4(0.f, 0.f, 0.f, 0.f);
    }

    float myS = 0.f;
    #pragma unroll
    for (int k = 0; k < 16; k++) {
        float s = v[k].x * w1v.x + v[k].y * w1v.y
                + v[k].z * w1v.z + v[k].w * w1v.w;
        // width-16 XOR butterfly = allreduce within each 16-lane half
        s += __shfl_xor_sync(0xffffffffu, s, 8, 16);
        s += __shfl_xor_sync(0xffffffffu, s, 4, 16);
        s += __shfl_xor_sync(0xffffffffu, s, 2, 16);
        s += __shfl_xor_sync(0xffffffffu, s, 1, 16);
        if (myk == k) myS = s;    // lane keeps its own pair's sum
    }
    if (!guard || p < NP)
        g_E0[p] = __expf(leaky(myS + b1v) + mk);
}

__global__ __launch_bounds__(K1_THREADS, 1)
void k1_lstm_rel(const float* __restrict__ x, const float* __restrict__ rel,
                 const float* __restrict__ mask,
                 const float* __restrict__ Wih, const float* __restrict__ Whh,
                 const float* __restrict__ bih, const float* __restrict__ bhh,
                 const float* __restrict__ w1, const float* __restrict__ b1p)
{
    extern __shared__ float sm[];
    const int tid = threadIdx.x;
    const int w = tid >> 5;
    const int bx = blockIdx.x;
    const bool lstmB = (bx < LSTM_BLOCKS);

    if (lstmB && w < 8) {
        // ---------------- LSTM role: 256 threads, 16 rows, f32x2 gates -------
        const int j  = tid & 63;
        const int rg = tid >> 6;
        const int r0 = rg * 4;
        const int row0 = bx * 16;

        float* Whh_P = sm + SM_WHH;
        float* Wih_P = sm + SM_WIH;
        float* x_s   = sm + SM_X;
        float* h_s   = sm + SM_H;

        for (int idx = tid; idx < 16384; idx += 256) {
            int gr = idx >> 6, k = idx & 63;
            int gate = gr >> 6, jj = gr & 63;
            Whh_P[((k << 6) + jj) * 4 + gate] = Whh[idx];
        }
        for (int idx = tid; idx < 4096; idx += 256) {
            int gr = idx >> 4, d = idx & 15;
            int gate = gr >> 6, jj = gr & 63;
            Wih_P[((d << 6) + jj) * 4 + gate] = Wih[idx];
        }
        for (int idx = tid; idx < 16 * TT * DD; idx += 256)
            x_s[idx] = x[(size_t)row0 * TT * DD + idx];
        for (int idx = tid; idx < 2048; idx += 256) h_s[idx] = 0.f;

        const unsigned long long bIF = pk2(bih[j] + bhh[j], bih[64 + j] + bhh[64 + j]);
        const unsigned long long bGO = pk2(bih[128 + j] + bhh[128 + j], bih[192 + j] + bhh[192 + j]);

        const unsigned int wih_a = smem_u32(Wih_P) + (unsigned)j * 16;
        const unsigned int whh_a = smem_u32(Whh_P) + (unsigned)j * 16;

        float c[4] = {0.f, 0.f, 0.f, 0.f};
        asm volatile("bar.sync 1, 256;" ::: "memory");

        int buf = 0;
        for (int t = 0; t < TT; t++) {
            unsigned long long aIF[4], aGO[4];
            #pragma unroll
            for (int q = 0; q < 4; q++) { aIF[q] = bIF; aGO[q] = bGO; }

            const float* xb = x_s + t * DD;
            #pragma unroll
            for (int d = 0; d < DD; d++) {
                unsigned long long wIF, wGO;
                lds2x64(wIF, wGO, wih_a + (unsigned)d * 1024);
                #pragma unroll
                for (int q = 0; q < 4; q++) {
                    float xv = xb[(r0 + q) * 256 + d];
                    unsigned long long x2 = pk2(xv, xv);
                    fma2(aIF[q], wIF, x2);
                    fma2(aGO[q], wGO, x2);
                }
            }
            const float* hb = h_s + buf * 1024;
            #pragma unroll 8
            for (int k = 0; k < HH; k++) {
                unsigned long long wIF, wGO;
                lds2x64(wIF, wGO, whh_a + (unsigned)k * 1024);
                #pragma unroll
                for (int q = 0; q < 4; q++) {
                    float hv = hb[(r0 + q) * 64 + k];
                    unsigned long long h2 = pk2(hv, hv);
                    fma2(aIF[q], wIF, h2);
                    fma2(aGO[q], wGO, h2);
                }
            }
            float* hn = h_s + (buf ^ 1) * 1024;
            #pragma unroll
            for (int q = 0; q < 4; q++) {
                float ai, af, ag, ao;
                upk2(ai, af, aIF[q]);
                upk2(ag, ao, aGO[q]);
                float ig = sigm(ai);
                float fg = sigm(af);
                float gg = tanhx(ag);
                float og = sigm(ao);
                c[q] = fmaf(fg, c[q], ig * gg);
                float hv = og * tanhx(c[q]);
                hn[(r0 + q) * 64 + j] = hv;
                if (t == TT - 1) g_emb[(size_t)(row0 + r0 + q) * 64 + j] = hv;
            }
            asm volatile("bar.sync 1, 256;" ::: "memory");
            buf ^= 1;
        }
    } else {
        // ---------------- relation role: global-only, shuffle reduce ---------
        const int rw = lstmB ? (bx * 16 + (w - 8))
                             : (LSTM_BLOCKS * 16 + (bx - LSTM_BLOCKS) * 24 + w);
        const int lane = tid & 31;
        const int sub  = lane & 15;
        float4 w1v = *(const float4*)(w1 + sub * 4);
        float b1v = __ldg(b1p);
        const float4* rel4 = (const float4*)rel;

        const long stride = (long)NRELW * 16;
        long base = (long)rw * 16;
        for (; base + 16 <= NP2; base += stride)
            rel_batch(rel4, mask, base, lane, w1v, b1v, false);
        if (base < NP2)
            rel_batch(rel4, mask, base, lane, w1v, b1v, true);
    }
}

// ---------------- K2b: fused era + column-sum partials -----------------------
// grid (NN/256=8, 16): bx = j-block of 256, by = row chunk of 128
__global__ __launch_bounds__(256) void k2b_colsum(
    const float* __restrict__ w2, const float* __restrict__ b2,
    const float* __restrict__ w3, const float* __restrict__ b3)
{
    __shared__ float w2s[64], w3s[64], era_s[128];
    int tid = threadIdx.x;
    if (tid < 64) { w2s[tid] = w2[tid]; w3s[tid] = w3[tid]; }
    __syncthreads();
    int i0 = blockIdx.y * 128;
    if (tid < 128) {
        const float4* e4 = (const float4*)(g_emb + (size_t)(i0 + tid) * 64);
        float s2 = 0.f, s3 = 0.f;
        #pragma unroll
        for (int k = 0; k < 16; k++) {
            float4 e = e4[k];
            float4 a = ((const float4*)w2s)[k];
            float4 b = ((const float4*)w3s)[k];
            s2 += e.x*a.x + e.y*a.y + e.z*a.z + e.w*a.w;
            s3 += e.x*b.x + e.y*b.y + e.z*b.z + e.w*b.w;
        }
        s2 += __ldg(b2); s3 += __ldg(b3);
        float era = __expf(leaky(s2) + leaky(s3));
        era_s[tid] = era;
        if (blockIdx.x == 0) g_era[i0 + tid] = era;
    }
    __syncthreads();
    int j = blockIdx.x * 256 + tid;
    float acc = 0.f;
    #pragma unroll 8
    for (int r = 0; r < 128; r++)
        acc = fmaf(era_s[r], g_E0[(size_t)(i0 + r) * NN + j], acc);
    g_zpart[blockIdx.y * NN + j] = acc;
}

// ---------------- K3q: q[j] = iZ_j*(emb[j].w4b); base[j] = b4 + emb[j].w4a ---
__global__ __launch_bounds__(128) void k3_q(const float* __restrict__ w4,
                                            const float* __restrict__ b4)
{
    __shared__ float w4s[128];
    int tid = threadIdx.x;
    w4s[tid] = w4[tid];
    __syncthreads();
    int j = blockIdx.x * 128 + tid;
    float s = 0.f;
    #pragma unroll
    for (int c = 0; c < 16; c++) s += g_zpart[c * NN + j];
    float iZ = __fdividef(1.f, s);
    const float4* e4 = (const float4*)(g_emb + (size_t)j * 64);
    float da = 0.f, db = 0.f;
    #pragma unroll
    for (int k = 0; k < 16; k++) {
        float4 e = e4[k];
        float4 wa = ((const float4*)w4s)[k];
        float4 wb = ((const float4*)w4s)[16 + k];
        da += e.x*wa.x + e.y*wa.y + e.z*wa.z + e.w*wa.w;
        db += e.x*wb.x + e.y*wb.y + e.z*wb.z + e.w*wb.w;
    }
    g_q[j] = iZ * db;
    g_base[j] = __ldg(b4) + da;
}

// ---------------- K4f: out[i] = leaky(base_i + era_i * sum_j E0[i,j]*q_j) ----
// grid 128 blocks x 256 threads; one warp per row, 2 rows per warp
__global__ __launch_bounds__(256) void k4_final(float* __restrict__ out)
{
    __shared__ __align__(16) float q_s[NN];
    int tid = threadIdx.x;
    int wid = tid >> 5, lane = tid & 31;
    for (int idx = tid; idx < NN / 4; idx += 256)
        ((float4*)q_s)[idx] = ((const float4*)g_q)[idx];
    __syncthreads();

    #pragma unroll
    for (int r = 0; r < 2; r++) {
        int i = blockIdx.x * 16 + wid * 2 + r;
        const float4* e0 = (const float4*)(g_E0 + (size_t)i * NN) + lane;
        const float4* q4 = (const float4*)q_s + lane;
        float acc = 0.f;
        #pragma unroll
        for (int m = 0; m < 16; m++) {
            float4 v = __ldg(e0 + m * 32);
            float4 qv = q4[m * 32];
            acc += v.x*qv.x + v.y*qv.y + v.z*qv.z + v.w*qv.w;
        }
        #pragma unroll
        for (int d = 16; d; d >>= 1)
            acc += __shfl_xor_sync(0xffffffffu, acc, d);
        if (lane == 0)
            out[i] = leaky(g_base[i] + __ldg(g_era + i) * acc);
    }
}

// ---------------- launch ------------------------------------------------------
extern "C" void kernel_launch(void* const* d_in, const int* in_sizes, int n_in,
                              void* d_out, int out_size)
{
    const float* x    = (const float*)d_in[0];
    const float* rel  = (const float*)d_in[1];
    const float* mask = (const float*)d_in[2];
    const float* Wih  = (const float*)d_in[3];
    const float* Whh  = (const float*)d_in[4];
    const float* bih  = (const float*)d_in[5];
    const float* bhh  = (const float*)d_in[6];
    const float* w1   = (const float*)d_in[7];
    const float* b1   = (const float*)d_in[8];
    const float* w2   = (const float*)d_in[9];
    const float* b2   = (const float*)d_in[10];
    const float* w3   = (const float*)d_in[11];
    const float* b3   = (const float*)d_in[12];
    const float* w4   = (const float*)d_in[13];
    const float* b4   = (const float*)d_in[14];

    cudaFuncSetAttribute(k1_lstm_rel, cudaFuncAttributeMaxDynamicSharedMemorySize,
                         SM_TOT * (int)sizeof(float));

    k1_lstm_rel<<<K1_BLOCKS, K1_THREADS, SM_TOT * sizeof(float)>>>(
        x, rel, mask, Wih, Whh, bih, bhh, w1, b1);
    k2b_colsum<<<dim3(NN / 256, 16), 256>>>(w2, b2, w3, b3);
    k3_q<<<NN / 128, 128>>>(w4, b4);
    k4_final<<<128, 256>>>((float*)d_out);
}

// round 10
// speedup vs baseline: 1.7595x; 1.0084x over previous
#include <cuda_runtime.h>
#include <cstdint>

#define NN 2048
#define TT 16
#define DD 16
#define HH 64
#define NP (NN*NN)          // 4194304 pairs
#define NP2 (NP/2)          // 2097152 pair-pairs (512B each)
#define NBATCH (NP2/16)     // 131072 batches (16 p2 = 32 pairs = 8KB each)
#define CHUNK 4             // batches per atomic grab
#define NCHUNK (NBATCH/CHUNK)

// ---------------- device scratch (static, no allocation) ----------------
__device__ __align__(16) float g_E0[NP];          // 16 MB: exp(leaky(rel.w1+b1)+mask)
__device__ __align__(16) float g_emb[NN*HH];      // LSTM last hidden
__device__ __align__(16) float g_era[NN];         // exp(leaky(emb.w2+b2)+leaky(emb.w3+b3))
__device__ __align__(16) float g_zpart[16*NN];    // column-sum partials (16 row-chunks)
__device__ __align__(16) float g_q[NN];           // iZ_j * (emb[j].w4b)
__device__ __align__(16) float g_base[NN];        // b4 + emb[j].w4a
__device__ unsigned int g_cnt = 0;                // rel work-steal counter

__device__ __forceinline__ float sigm(float v) {
    v = fminf(fmaxf(v, -30.f), 30.f);
    return __fdividef(1.f, 1.f + __expf(-v));
}
__device__ __forceinline__ float tanhx(float v) {
    v = fminf(fmaxf(v, -30.f), 30.f);
    float e = __expf(-2.f * v);
    return __fdividef(1.f - e, 1.f + e);
}
__device__ __forceinline__ float leaky(float v) { return fmaxf(0.2f * v, v); }

// f32x2 helpers
__device__ __forceinline__ void fma2(unsigned long long& acc,
                                     unsigned long long a, unsigned long long b) {
    asm("fma.rn.f32x2 %0, %1, %2, %0;" : "+l"(acc) : "l"(a), "l"(b));
}
__device__ __forceinline__ unsigned long long pk2(float x, float y) {
    unsigned long long r;
    asm("mov.b64 %0, {%1, %2};" : "=l"(r) : "f"(x), "f"(y));
    return r;
}
__device__ __forceinline__ void upk2(float& x, float& y, unsigned long long v) {
    asm("mov.b64 {%0, %1}, %2;" : "=f"(x), "=f"(y) : "l"(v));
}
__device__ __forceinline__ void lds2x64(unsigned long long& a, unsigned long long& b,
                                        unsigned int addr) {
    asm volatile("ld.shared.v2.b64 {%0, %1}, [%2];" : "=l"(a), "=l"(b) : "r"(addr));
}
__device__ __forceinline__ unsigned int smem_u32(const void* p) {
    unsigned int a;
    asm("{ .reg .u64 t; cvta.to.shared.u64 t, %1; cvt.u32.u64 %0, t; }" : "=r"(a) : "l"(p));
    return a;
}

// ---------------- K1: fused LSTM + work-stealing relation stream -------------
#define K1_BLOCKS 148
#define LSTM_BLOCKS 128
#define K1_THREADS 768

// smem float offsets (LSTM blocks only use these)
#define SM_WHH 0          // 64*64*4 floats (layout [(k*64+j)*4 + gate])
#define SM_WIH 16384      // 16*64*4
#define SM_X   20480      // 16 rows * 256
#define SM_H   24576      // 2 * 16 * 64
#define SM_TOT 26624      // floats -> 106496 bytes

// one batch of 16 pair-pairs (32 pairs = 8KB of rel); MLP=16, no guard needed
__device__ __forceinline__ void rel_batch(
    const float4* __restrict__ rel4, const float* __restrict__ mask,
    long base, int lane, float4 w1v, float b1v)
{
    const int myk = lane & 15;
    long p = 2 * base + 2 * myk + (lane >> 4);
    float mk = __ldcs(mask + p);

    float4 v[16];
    const float4* src = rel4 + base * 32 + lane;
    #pragma unroll
    for (int k = 0; k < 16; k++) v[k] = __ldcs(src + k * 32);

    float myS = 0.f;
    #pragma unroll
    for (int k = 0; k < 16; k++) {
        float s = v[k].x * w1v.x + v[k].y * w1v.y
                + v[k].z * w1v.z + v[k].w * w1v.w;
        // width-16 XOR butterfly = allreduce within each 16-lane half
        s += __shfl_xor_sync(0xffffffffu, s, 8, 16);
        s += __shfl_xor_sync(0xffffffffu, s, 4, 16);
        s += __shfl_xor_sync(0xffffffffu, s, 2, 16);
        s += __shfl_xor_sync(0xffffffffu, s, 1, 16);
        if (myk == k) myS = s;    // lane keeps its own pair's sum
    }
    g_E0[p] = __expf(leaky(myS + b1v) + mk);
}

// work-steal loop: every warp pulls CHUNK-batch chunks until exhausted
__device__ __forceinline__ void rel_loop(
    const float4* __restrict__ rel4, const float* __restrict__ mask,
    int lane, float4 w1v, float b1v)
{
    for (;;) {
        unsigned int c;
        if (lane == 0) c = atomicAdd(&g_cnt, 1u);
        c = __shfl_sync(0xffffffffu, c, 0);
        if (c >= NCHUNK) break;
        long base0 = (long)c * (CHUNK * 16);
        #pragma unroll
        for (int b = 0; b < CHUNK; b++)
            rel_batch(rel4, mask, base0 + b * 16, lane, w1v, b1v);
    }
}

__global__ __launch_bounds__(K1_THREADS, 1)
void k1_lstm_rel(const float* __restrict__ x, const float* __restrict__ rel,
                 const float* __restrict__ mask,
                 const float* __restrict__ Wih, const float* __restrict__ Whh,
                 const float* __restrict__ bih, const float* __restrict__ bhh,
                 const float* __restrict__ w1, const float* __restrict__ b1p)
{
    extern __shared__ float sm[];
    const int tid = threadIdx.x;
    const int w = tid >> 5;
    const int bx = blockIdx.x;
    const bool lstmB = (bx < LSTM_BLOCKS);
    const int lane = tid & 31;
    const int sub = lane & 15;
    const float4 w1v = *(const float4*)(w1 + sub * 4);
    const float b1v = __ldg(b1p);
    const float4* rel4 = (const float4*)rel;

    if (lstmB && w < 8) {
        // ---------------- LSTM role: 256 threads, 16 rows, f32x2 gates -------
        const int j  = tid & 63;
        const int rg = tid >> 6;
        const int r0 = rg * 4;
        const int row0 = bx * 16;

        float* Whh_P = sm + SM_WHH;
        float* Wih_P = sm + SM_WIH;
        float* x_s   = sm + SM_X;
        float* h_s   = sm + SM_H;

        for (int idx = tid; idx < 16384; idx += 256) {
            int gr = idx >> 6, k = idx & 63;
            int gate = gr >> 6, jj = gr & 63;
            Whh_P[((k << 6) + jj) * 4 + gate] = Whh[idx];
        }
        for (int idx = tid; idx < 4096; idx += 256) {
            int gr = idx >> 4, d = idx & 15;
            int gate = gr >> 6, jj = gr & 63;
            Wih_P[((d << 6) + jj) * 4 + gate] = Wih[idx];
        }
        for (int idx = tid; idx < 16 * TT * DD; idx += 256)
            x_s[idx] = x[(size_t)row0 * TT * DD + idx];
        for (int idx = tid; idx < 2048; idx += 256) h_s[idx] = 0.f;

        const unsigned long long bIF = pk2(bih[j] + bhh[j], bih[64 + j] + bhh[64 + j]);
        const unsigned long long bGO = pk2(bih[128 + j] + bhh[128 + j], bih[192 + j] + bhh[192 + j]);

        const unsigned int wih_a = smem_u32(Wih_P) + (unsigned)j * 16;
        const unsigned int whh_a = smem_u32(Whh_P) + (unsigned)j * 16;

        float c[4] = {0.f, 0.f, 0.f, 0.f};
        asm volatile("bar.sync 1, 256;" ::: "memory");

        int buf = 0;
        for (int t = 0; t < TT; t++) {
            unsigned long long aIF[4], aGO[4];
            #pragma unroll
            for (int q = 0; q < 4; q++) { aIF[q] = bIF; aGO[q] = bGO; }

            const float* xb = x_s + t * DD;
            #pragma unroll
            for (int d = 0; d < DD; d++) {
                unsigned long long wIF, wGO;
                lds2x64(wIF, wGO, wih_a + (unsigned)d * 1024);
                #pragma unroll
                for (int q = 0; q < 4; q++) {
                    float xv = xb[(r0 + q) * 256 + d];
                    unsigned long long x2 = pk2(xv, xv);
                    fma2(aIF[q], wIF, x2);
                    fma2(aGO[q], wGO, x2);
                }
            }
            const float* hb = h_s + buf * 1024;
            #pragma unroll 8
            for (int k = 0; k < HH; k++) {
                unsigned long long wIF, wGO;
                lds2x64(wIF, wGO, whh_a + (unsigned)k * 1024);
                #pragma unroll
                for (int q = 0; q < 4; q++) {
                    float hv = hb[(r0 + q) * 64 + k];
                    unsigned long long h2 = pk2(hv, hv);
                    fma2(aIF[q], wIF, h2);
                    fma2(aGO[q], wGO, h2);
                }
            }
            float* hn = h_s + (buf ^ 1) * 1024;
            #pragma unroll
            for (int q = 0; q < 4; q++) {
                float ai, af, ag, ao;
                upk2(ai, af, aIF[q]);
                upk2(ag, ao, aGO[q]);
                float ig = sigm(ai);
                float fg = sigm(af);
                float gg = tanhx(ag);
                float og = sigm(ao);
                c[q] = fmaf(fg, c[q], ig * gg);
                float hv = og * tanhx(c[q]);
                hn[(r0 + q) * 64 + j] = hv;
                if (t == TT - 1) g_emb[(size_t)(row0 + r0 + q) * 64 + j] = hv;
            }
            asm volatile("bar.sync 1, 256;" ::: "memory");
            buf ^= 1;
        }
        // LSTM done -> join the relation stream
        rel_loop(rel4, mask, lane, w1v, b1v);
    } else {
        // dedicated relation warps start immediately
        rel_loop(rel4, mask, lane, w1v, b1v);
    }
}

// ---------------- K2b: fused era + column-sum partials -----------------------
// grid (NN/256=8, 16): bx = j-block of 256, by = row chunk of 128
__global__ __launch_bounds__(256) void k2b_colsum(
    const float* __restrict__ w2, const float* __restrict__ b2,
    const float* __restrict__ w3, const float* __restrict__ b3)
{
    __shared__ float w2s[64], w3s[64], era_s[128];
    int tid = threadIdx.x;
    if (tid < 64) { w2s[tid] = w2[tid]; w3s[tid] = w3[tid]; }
    __syncthreads();
    int i0 = blockIdx.y * 128;
    if (tid < 128) {
        const float4* e4 = (const float4*)(g_emb + (size_t)(i0 + tid) * 64);
        float s2 = 0.f, s3 = 0.f;
        #pragma unroll
        for (int k = 0; k < 16; k++) {
            float4 e = e4[k];
            float4 a = ((const float4*)w2s)[k];
            float4 b = ((const float4*)w3s)[k];
            s2 += e.x*a.x + e.y*a.y + e.z*a.z + e.w*a.w;
            s3 += e.x*b.x + e.y*b.y + e.z*b.z + e.w*b.w;
        }
        s2 += __ldg(b2); s3 += __ldg(b3);
        float era = __expf(leaky(s2) + leaky(s3));
        era_s[tid] = era;
        if (blockIdx.x == 0) g_era[i0 + tid] = era;
    }
    __syncthreads();
    int j = blockIdx.x * 256 + tid;
    float acc = 0.f;
    #pragma unroll 8
    for (int r = 0; r < 128; r++)
        acc = fmaf(era_s[r], g_E0[(size_t)(i0 + r) * NN + j], acc);
    g_zpart[blockIdx.y * NN + j] = acc;
}

// ---------------- K3q: q[j] = iZ_j*(emb[j].w4b); base[j] = b4 + emb[j].w4a ---
__global__ __launch_bounds__(128) void k3_q(const float* __restrict__ w4,
                                            const float* __restrict__ b4)
{
    __shared__ float w4s[128];
    int tid = threadIdx.x;
    w4s[tid] = w4[tid];
    __syncthreads();
    int j = blockIdx.x * 128 + tid;
    float s = 0.f;
    #pragma unroll
    for (int c = 0; c < 16; c++) s += g_zpart[c * NN + j];
    float iZ = __fdividef(1.f, s);
    const float4* e4 = (const float4*)(g_emb + (size_t)j * 64);
    float da = 0.f, db = 0.f;
    #pragma unroll
    for (int k = 0; k < 16; k++) {
        float4 e = e4[k];
        float4 wa = ((const float4*)w4s)[k];
        float4 wb = ((const float4*)w4s)[16 + k];
        da += e.x*wa.x + e.y*wa.y + e.z*wa.z + e.w*wa.w;
        db += e.x*wb.x + e.y*wb.y + e.z*wb.z + e.w*wb.w;
    }
    g_q[j] = iZ * db;
    g_base[j] = __ldg(b4) + da;
}

// ---------------- K4f: out[i] = leaky(base_i + era_i * sum_j E0[i,j]*q_j) ----
// grid 512 blocks x 128 threads; one warp per row
__global__ __launch_bounds__(128) void k4_final(float* __restrict__ out)
{
    int tid = threadIdx.x;
    int wid = tid >> 5, lane = tid & 31;
    if (blockIdx.x == 0 && tid == 0) g_cnt = 0;   // reset work-steal counter for next replay

    int i = blockIdx.x * 4 + wid;
    const float4* e0 = (const float4*)(g_E0 + (size_t)i * NN) + lane;
    const float4* q4 = (const float4*)g_q + lane;
    float acc = 0.f;
    #pragma unroll
    for (int m = 0; m < 16; m++) {
        float4 v = __ldg(e0 + m * 32);
        float4 qv = __ldg(q4 + m * 32);
        acc += v.x*qv.x + v.y*qv.y + v.z*qv.z + v.w*qv.w;
    }
    #pragma unroll
    for (int d = 16; d; d >>= 1)
        acc += __shfl_xor_sync(0xffffffffu, acc, d);
    if (lane == 0)
        out[i] = leaky(g_base[i] + __ldg(g_era + i) * acc);
}

// ---------------- launch ------------------------------------------------------
extern "C" void kernel_launch(void* const* d_in, const int* in_sizes, int n_in,
                              void* d_out, int out_size)
{
    const float* x    = (const float*)d_in[0];
    const float* rel  = (const float*)d_in[1];
    const float* mask = (const float*)d_in[2];
    const float* Wih  = (const float*)d_in[3];
    const float* Whh  = (const float*)d_in[4];
    const float* bih  = (const float*)d_in[5];
    const float* bhh  = (const float*)d_in[6];
    const float* w1   = (const float*)d_in[7];
    const float* b1   = (const float*)d_in[8];
    const float* w2   = (const float*)d_in[9];
    const float* b2   = (const float*)d_in[10];
    const float* w3   = (const float*)d_in[11];
    const float* b3   = (const float*)d_in[12];
    const float* w4   = (const float*)d_in[13];
    const float* b4   = (const float*)d_in[14];

    cudaFuncSetAttribute(k1_lstm_rel, cudaFuncAttributeMaxDynamicSharedMemorySize,
                         SM_TOT * (int)sizeof(float));

    k1_lstm_rel<<<K1_BLOCKS, K1_THREADS, SM_TOT * sizeof(float)>>>(
        x, rel, mask, Wih, Whh, bih, bhh, w1, b1);
    k2b_colsum<<<dim3(NN / 256, 16), 256>>>(w2, b2, w3, b3);
    k3_q<<<NN / 128, 128>>>(w4, b4);
    k4_final<<<NN / 4, 128>>>((float*)d_out);
}